// round 6
// baseline (speedup 1.0000x reference)
#include <cuda_runtime.h>
#include <cuda_bf16.h>
#include <cstdint>
#include <cstddef>

// Problem constants
#define VV 32000
#define EE 512
#define HH 1024
#define NN 32
#define TT 256
#define TS 255            // timesteps = T-1
#define VBLK 64           // vocab columns per block in logits kernel
#define NBV (VV / VBLK)   // 500 blocks over vocab

// ---------------- scratch (device globals; no allocation allowed) ----------------
__device__ float g_WT[(size_t)HH * VV];          // emit_w transposed: [K][V], 131 MB
__device__ float g_h[2][HH * NN];                // hidden state transposed: h[k*32+n], ping-pong
__device__ float g_Spart[(size_t)TS * NBV * NN]; // per-(t, block) partial sum-of-exp, 16.3 MB
__device__ float g_tgt[TS * NN];                 // target logit per (t, n)

// ---------------- prologue: transpose emit_w [V][K] -> g_WT [K][V] ----------------
__global__ void transpose_kernel(const float* __restrict__ emit_w) {
    __shared__ float tile[32][33];
    int tx = threadIdx.x;            // 0..31
    int ty = threadIdx.y;            // 0..7
    int v0 = blockIdx.x * 32;        // 1000 tiles over V
    int k0 = blockIdx.y * 32;        // 32 tiles over K
    #pragma unroll
    for (int r = ty; r < 32; r += 8)
        tile[r][tx] = __ldg(emit_w + (size_t)(v0 + r) * HH + k0 + tx);
    __syncthreads();
    #pragma unroll
    for (int r = ty; r < 32; r += 8)
        g_WT[(size_t)(k0 + r) * VV + v0 + tx] = tile[tx][r];
}

// ---------------- prologue: init transposed hidden state ----------------
__global__ void hinit_kernel(const float* __restrict__ hidden) {
    int idx = blockIdx.x * blockDim.x + threadIdx.x;   // 0..32767
    if (idx < HH * NN) {
        int n = idx & 31;
        int j = idx >> 5;
        g_h[0][j * NN + n] = hidden[n * HH + j];
    }
}

// ---------------- per-step: GRU cell ----------------
// grid 128 x 256 -> 1024 warps, warp gw handles output feature j = gw, lane = n.
__global__ void gru_kernel(const int* __restrict__ words,
                           const float* __restrict__ embed_w,
                           const float* __restrict__ w_ih,
                           const float* __restrict__ w_hh,
                           const float* __restrict__ b_ih,
                           const float* __restrict__ b_hh,
                           int t) {
    int lane = threadIdx.x & 31;
    int j = blockIdx.x * 8 + (threadIdx.x >> 5);

    const float* __restrict__ hold = g_h[t & 1];
    float* __restrict__ hnew = g_h[(t + 1) & 1];

    int word = __ldg(words + lane * TT + t);
    const float* xr = embed_w + (size_t)word * EE;

    const float* wr = w_ih + (size_t)j * EE;
    const float* wz = w_ih + (size_t)(HH + j) * EE;
    const float* wn = w_ih + (size_t)(2 * HH + j) * EE;

    float gr = __ldg(b_ih + j);
    float gz = __ldg(b_ih + HH + j);
    float gn = __ldg(b_ih + 2 * HH + j);

    #pragma unroll 4
    for (int k = 0; k < EE; k += 4) {
        float4 x4 = __ldg(reinterpret_cast<const float4*>(xr + k));
        float4 a = __ldg(reinterpret_cast<const float4*>(wr + k));
        float4 b = __ldg(reinterpret_cast<const float4*>(wz + k));
        float4 c = __ldg(reinterpret_cast<const float4*>(wn + k));
        gr += a.x * x4.x + a.y * x4.y + a.z * x4.z + a.w * x4.w;
        gz += b.x * x4.x + b.y * x4.y + b.z * x4.z + b.w * x4.w;
        gn += c.x * x4.x + c.y * x4.y + c.z * x4.z + c.w * x4.w;
    }

    const float* ur = w_hh + (size_t)j * HH;
    const float* uz = w_hh + (size_t)(HH + j) * HH;
    const float* un = w_hh + (size_t)(2 * HH + j) * HH;

    float hr = __ldg(b_hh + j);
    float hz = __ldg(b_hh + HH + j);
    float hn = __ldg(b_hh + 2 * HH + j);

    #pragma unroll 4
    for (int k = 0; k < HH; k += 4) {
        float h0 = __ldg(hold + (k + 0) * NN + lane);
        float h1 = __ldg(hold + (k + 1) * NN + lane);
        float h2 = __ldg(hold + (k + 2) * NN + lane);
        float h3 = __ldg(hold + (k + 3) * NN + lane);
        float4 a = __ldg(reinterpret_cast<const float4*>(ur + k));
        float4 b = __ldg(reinterpret_cast<const float4*>(uz + k));
        float4 c = __ldg(reinterpret_cast<const float4*>(un + k));
        hr += a.x * h0 + a.y * h1 + a.z * h2 + a.w * h3;
        hz += b.x * h0 + b.y * h1 + b.z * h2 + b.w * h3;
        hn += c.x * h0 + c.y * h1 + c.z * h2 + c.w * h3;
    }

    float r = 1.0f / (1.0f + expf(-(gr + hr)));
    float z = 1.0f / (1.0f + expf(-(gz + hz)));
    float nn_ = tanhf(gn + r * hn);
    float ho = hold[j * NN + lane];
    hnew[j * NN + lane] = (1.0f - z) * nn_ + z * ho;
}

// ---------------- per-step: logits + partial sum-of-exp + target extraction ----------------
// grid 500 x 256. lane = n, warp handles 8 consecutive vocab columns.
__global__ void logits_kernel(const int* __restrict__ words,
                              const float* __restrict__ emit_b,
                              int t) {
    int lane = threadIdx.x & 31;
    int w = threadIdx.x >> 5;
    int v0 = blockIdx.x * VBLK + w * 8;

    const float* __restrict__ hp = g_h[(t + 1) & 1] + lane;
    const float4* __restrict__ wp = reinterpret_cast<const float4*>(g_WT + v0);

    float a0 = 0.f, a1 = 0.f, a2 = 0.f, a3 = 0.f;
    float a4 = 0.f, a5 = 0.f, a6 = 0.f, a7 = 0.f;

    #pragma unroll 4
    for (int k = 0; k < HH; ++k) {
        float hv = __ldg(hp);
        hp += NN;
        float4 wa = __ldcs(wp);
        float4 wb = __ldcs(wp + 1);
        wp += VV / 4;
        a0 += wa.x * hv; a1 += wa.y * hv; a2 += wa.z * hv; a3 += wa.w * hv;
        a4 += wb.x * hv; a5 += wb.y * hv; a6 += wb.z * hv; a7 += wb.w * hv;
    }

    int tgt = __ldg(words + lane * TT + t + 1);
    float acc[8] = {a0, a1, a2, a3, a4, a5, a6, a7};
    float s = 0.f;
    #pragma unroll
    for (int i = 0; i < 8; ++i) {
        float logit = acc[i] + __ldg(emit_b + v0 + i);
        s += __expf(logit);                 // logits are O(1): no max-shift needed
        if (v0 + i == tgt) g_tgt[t * NN + lane] = logit;
    }

    __shared__ float red[8][NN];
    red[w][lane] = s;
    __syncthreads();
    if (w == 0) {
        float tot = 0.f;
        #pragma unroll
        for (int r = 0; r < 8; ++r) tot += red[r][lane];
        g_Spart[((size_t)t * NBV + blockIdx.x) * NN + lane] = tot;
    }
}

// ---------------- epilogue: deterministic reduction + output write ----------------
// grid 32 blocks (one per n) x 256 threads.
__global__ void finalize_kernel(float* __restrict__ out, int out_size) {
    int n = blockIdx.x;
    int tid = threadIdx.x;

    float local = 0.f;
    if (tid < TS) {
        int t = tid;
        float S = 0.f;
        const float* sp = g_Spart + (size_t)t * NBV * NN + n;
        for (int b = 0; b < NBV; ++b) S += sp[b * NN];
        local = g_tgt[t * NN + n] - logf(S);
    }

    __shared__ float sred[256];
    sred[tid] = local;
    __syncthreads();
    #pragma unroll
    for (int s = 128; s > 0; s >>= 1) {
        if (tid < s) sred[tid] += sred[tid + s];
        __syncthreads();
    }

    if (tid == 0 && out_size >= NN) out[n] = sred[0];

    // h_final (transposed buffer -> [N, H]); last step wrote g_h[TS & 1] = g_h[1]
    if (out_size >= NN + NN * HH) {
        const float* hf = g_h[TS & 1];
        for (int j = tid; j < HH; j += 256)
            out[NN + n * HH + j] = hf[j * NN + n];
    }
}

// ---------------- launcher (graph-capturable: kernel launches only) ----------------
extern "C" void kernel_launch(void* const* d_in, const int* in_sizes, int n_in,
                              void* d_out, int out_size) {
    const int*   words  = (const int*)  d_in[0];
    const float* hidden = (const float*)d_in[1];
    const float* embed  = (const float*)d_in[2];
    const float* w_ih   = (const float*)d_in[3];
    const float* w_hh   = (const float*)d_in[4];
    const float* b_ih   = (const float*)d_in[5];
    const float* b_hh   = (const float*)d_in[6];
    const float* emit_w = (const float*)d_in[7];
    const float* emit_b = (const float*)d_in[8];
    float* out = (float*)d_out;

    // Prologue: transpose emit weights, init transposed hidden state.
    transpose_kernel<<<dim3(VV / 32, HH / 32), dim3(32, 8)>>>(emit_w);
    hinit_kernel<<<(HH * NN + 255) / 256, 256>>>(hidden);

    // 255 sequential timesteps, 2 kernels each (same stream -> serialized in graph).
    for (int t = 0; t < TS; ++t) {
        gru_kernel<<<HH / 8, 256>>>(words, embed, w_ih, w_hh, b_ih, b_hh, t);
        logits_kernel<<<NBV, 256>>>(words, emit_b, t);
    }

    // Epilogue: deterministic reduction and output.
    finalize_kernel<<<NN, 256>>>(out, out_size);
}

// round 7
// speedup vs baseline: 6.7014x; 6.7014x over previous
#include <cuda_runtime.h>
#include <cuda_bf16.h>
#include <cstdint>
#include <cstddef>

// Problem constants
#define VV 32000
#define EE 512
#define HH 1024
#define NN 32
#define TT 256
#define TS 255            // timesteps = T-1
#define NBV 500           // logits blocks (64 vocab cols each)

// ---------------- scratch (device globals; no allocation allowed) ----------------
__device__ __nv_bfloat16 g_Wpk[(size_t)VV * HH];    // emit_w bf16, mma B-fragment-major, 65.5 MB
__device__ float g_gi[(size_t)TS * 3 * HH * NN];    // precomputed input gates gi[t][g*H+j][n], 100 MB
__device__ float g_h[2][HH * NN];                   // hidden, PAIR layout: ((j>>1)*64 + n*2 + (j&1))
__device__ __nv_bfloat16 g_hfrag[2 * 64 * 32 * 8];  // h as mma A-fragments (2 mtiles x 64 ktiles), 64 KB
__device__ float g_Spart[(size_t)TS * NBV * NN];    // per-(t,block) partial sum-of-exp
__device__ float g_tgt[TS * NN];                    // target logit per (t, n)

// ---------------- prologue: pack emit_w [V][H] fp32 -> bf16 B-fragment-major ----------------
// For tile (bv = v/8, bk = k/16): lane = (v%8)*4 + ((k%16 & 7)>>1), reg = (k%16)>>3, half = k&1.
// bf16 index = ((bv*64 + bk)*32 + lane)*4 + reg*2 + half.
__global__ void pack_emit_kernel(const float* __restrict__ emit_w) {
    int v = blockIdx.x;
    int k = threadIdx.x;            // blockDim = 1024 = HH
    float val = __ldg(emit_w + (size_t)v * HH + k);
    int bv = v >> 3, nn = v & 7;
    int bk = k >> 4, kk = k & 15;
    int lane = nn * 4 + ((kk & 7) >> 1);
    int reg  = kk >> 3;
    int half = kk & 1;
    size_t idx = (((size_t)(bv * 64 + bk)) * 32 + lane) * 4 + reg * 2 + half;
    g_Wpk[idx] = __float2bfloat16(val);
}

// ---------------- prologue: init hidden state (pair layout) ----------------
__global__ void hinit_kernel(const float* __restrict__ hidden) {
    int idx = blockIdx.x * blockDim.x + threadIdx.x;   // 0..32767
    if (idx < HH * NN) {
        int n = idx & 31;
        int j = idx >> 5;
        g_h[0][(j >> 1) * 64 + n * 2 + (j & 1)] = hidden[n * HH + j];
    }
}

// ---------------- prologue: precompute gi[t] = x_t @ w_ih.T + b_ih for ALL t ----------------
// grid (128, 255), block 256: warp j = bx*8+w, t = by, lane = n.
__global__ void __launch_bounds__(256) gi_kernel(const int* __restrict__ words,
                                                 const float* __restrict__ embed_w,
                                                 const float* __restrict__ w_ih,
                                                 const float* __restrict__ b_ih) {
    int lane = threadIdx.x & 31;
    int j = blockIdx.x * 8 + (threadIdx.x >> 5);
    int t = blockIdx.y;

    int word = __ldg(words + lane * TT + t);
    const float* xr = embed_w + (size_t)word * EE;
    const float* wr = w_ih + (size_t)j * EE;
    const float* wz = w_ih + (size_t)(HH + j) * EE;
    const float* wn = w_ih + (size_t)(2 * HH + j) * EE;

    float gr = 0.f, gz = 0.f, gn = 0.f;
    #pragma unroll 4
    for (int k = 0; k < EE; k += 4) {
        float4 x4 = __ldg(reinterpret_cast<const float4*>(xr + k));
        float4 a = __ldg(reinterpret_cast<const float4*>(wr + k));
        float4 b = __ldg(reinterpret_cast<const float4*>(wz + k));
        float4 c = __ldg(reinterpret_cast<const float4*>(wn + k));
        gr += a.x * x4.x + a.y * x4.y + a.z * x4.z + a.w * x4.w;
        gz += b.x * x4.x + b.y * x4.y + b.z * x4.z + b.w * x4.w;
        gn += c.x * x4.x + c.y * x4.y + c.z * x4.z + c.w * x4.w;
    }
    size_t base = ((size_t)t * 3 * HH + j) * NN + lane;
    g_gi[base]               = gr + __ldg(b_ih + j);
    g_gi[base + (size_t)HH * NN]     = gz + __ldg(b_ih + HH + j);
    g_gi[base + (size_t)2 * HH * NN] = gn + __ldg(b_ih + 2 * HH + j);
}

// ---------------- per-step: GRU recurrent part (gh) + combine + emit h fragments ----------------
// grid 512, block 256 (8 warps). Block handles j0 = blockIdx*2 (2 features).
// warp w: jj = w&1 (which j), kq = w>>1 (k-quarter of 256). fp32 throughout.
__global__ void __launch_bounds__(256) gru_kernel(const float* __restrict__ w_hh,
                                                  const float* __restrict__ b_hh,
                                                  int t) {
    __shared__ float sp[4][2][3][NN];

    int lane = threadIdx.x & 31;
    int w = threadIdx.x >> 5;
    int jj = w & 1;
    int kq = w >> 1;
    int j0 = blockIdx.x * 2;
    int j = j0 + jj;

    const float* hold = g_h[t & 1];
    float* hnew = g_h[(t + 1) & 1];
    const float2* hp = reinterpret_cast<const float2*>(hold);

    const float4* wr = reinterpret_cast<const float4*>(w_hh + (size_t)j * HH);
    const float4* wz = reinterpret_cast<const float4*>(w_hh + (size_t)(HH + j) * HH);
    const float4* wn = reinterpret_cast<const float4*>(w_hh + (size_t)(2 * HH + j) * HH);

    float hr = 0.f, hz = 0.f, hn = 0.f;
    int m0 = kq * 128;                 // pair index range [m0, m0+128)
    #pragma unroll 4
    for (int m = m0; m < m0 + 128; m += 2) {
        float2 h0 = __ldg(hp + m * NN + lane);          // h[2m], h[2m+1]
        float2 h1 = __ldg(hp + (m + 1) * NN + lane);    // h[2m+2], h[2m+3]
        float4 a = __ldg(wr + (m >> 1));
        float4 b = __ldg(wz + (m >> 1));
        float4 c = __ldg(wn + (m >> 1));
        hr += a.x * h0.x + a.y * h0.y + a.z * h1.x + a.w * h1.y;
        hz += b.x * h0.x + b.y * h0.y + b.z * h1.x + b.w * h1.y;
        hn += c.x * h0.x + c.y * h0.y + c.z * h1.x + c.w * h1.y;
    }
    sp[kq][jj][0][lane] = hr;
    sp[kq][jj][1][lane] = hz;
    sp[kq][jj][2][lane] = hn;
    __syncthreads();

    if (w < 2) {
        int jc = j0 + w;
        float hrt = b_hh[jc], hzt = b_hh[HH + jc], hnt = b_hh[2 * HH + jc];
        #pragma unroll
        for (int q = 0; q < 4; ++q) {
            hrt += sp[q][w][0][lane];
            hzt += sp[q][w][1][lane];
            hnt += sp[q][w][2][lane];
        }
        size_t gib = ((size_t)t * 3 * HH + jc) * NN + lane;
        float gr = g_gi[gib];
        float gz = g_gi[gib + (size_t)HH * NN];
        float gn = g_gi[gib + (size_t)2 * HH * NN];

        float r = 1.0f / (1.0f + expf(-(gr + hrt)));
        float z = 1.0f / (1.0f + expf(-(gz + hzt)));
        float nn_ = tanhf(gn + r * hnt);
        float ho = hold[(jc >> 1) * 64 + lane * 2 + (jc & 1)];
        float hv = (1.0f - z) * nn_ + z * ho;

        // fp32 pair-layout store for next recurrence step
        hnew[(jc >> 1) * 64 + lane * 2 + (jc & 1)] = hv;

        // bf16 A-fragment store for the logits mma kernel (m = lane, k = jc)
        int mtile = lane >> 4, rr = lane & 15;
        int bkk = jc >> 4,     cc = jc & 15;
        int fl = (rr & 7) * 4 + ((cc & 7) >> 1);
        int rg = (rr >> 3) + 2 * (cc >> 3);
        int hf = cc & 1;
        g_hfrag[(((mtile * 64 + bkk) * 32 + fl) * 8) + rg * 2 + hf] = __float2bfloat16(hv);
    }
}

// ---------------- per-step: logits via mma.sync bf16 + sum-of-exp + target ----------------
// grid 500, block 256 (8 warps). warp handles one n8 vocab tile bv = blockIdx*8+w,
// both m16 tiles (batch = 32 rows), K = 1024 (64 k16 tiles).
__global__ void __launch_bounds__(256) logits_kernel(const int* __restrict__ words,
                                                     const float* __restrict__ emit_b,
                                                     int t) {
    __shared__ float sm[8][NN];

    int lane = threadIdx.x & 31;
    int w = threadIdx.x >> 5;
    int bv = blockIdx.x * 8 + w;
    int v0 = bv * 8;

    const uint4* Af = reinterpret_cast<const uint4*>(g_hfrag);
    const uint2* Bf = reinterpret_cast<const uint2*>(g_Wpk);

    float c0[4] = {0.f, 0.f, 0.f, 0.f};   // mtile 0 (rows 0..15)
    float c1[4] = {0.f, 0.f, 0.f, 0.f};   // mtile 1 (rows 16..31)

    #pragma unroll 4
    for (int bk = 0; bk < 64; ++bk) {
        uint4 a0 = Af[(0 * 64 + bk) * 32 + lane];
        uint4 a1 = Af[(1 * 64 + bk) * 32 + lane];
        uint2 b  = __ldg(Bf + ((size_t)bv * 64 + bk) * 32 + lane);
        asm volatile(
            "mma.sync.aligned.m16n8k16.row.col.f32.bf16.bf16.f32 "
            "{%0,%1,%2,%3}, {%4,%5,%6,%7}, {%8,%9}, {%0,%1,%2,%3};"
            : "+f"(c0[0]), "+f"(c0[1]), "+f"(c0[2]), "+f"(c0[3])
            : "r"(a0.x), "r"(a0.y), "r"(a0.z), "r"(a0.w), "r"(b.x), "r"(b.y));
        asm volatile(
            "mma.sync.aligned.m16n8k16.row.col.f32.bf16.bf16.f32 "
            "{%0,%1,%2,%3}, {%4,%5,%6,%7}, {%8,%9}, {%0,%1,%2,%3};"
            : "+f"(c1[0]), "+f"(c1[1]), "+f"(c1[2]), "+f"(c1[3])
            : "r"(a1.x), "r"(a1.y), "r"(a1.z), "r"(a1.w), "r"(b.x), "r"(b.y));
    }

    // Epilogue: element (row, col): c{mt}[e]: row = mt*16 + (lane>>2) + (e>=2 ? 8:0),
    //                               col = v0 + (lane&3)*2 + (e&1).
    int r0 = lane >> 2;
    int cbase = v0 + (lane & 3) * 2;
    float blo = __ldg(emit_b + cbase);
    float bhi = __ldg(emit_b + cbase + 1);
    int tw0 = __ldg(words + (r0)      * TT + t + 1);
    int tw1 = __ldg(words + (r0 + 8)  * TT + t + 1);
    int tw2 = __ldg(words + (r0 + 16) * TT + t + 1);
    int tw3 = __ldg(words + (r0 + 24) * TT + t + 1);

    float s0, s1, s2, s3;
    {
        float l00 = c0[0] + blo, l01 = c0[1] + bhi;   // row r0
        float l02 = c0[2] + blo, l03 = c0[3] + bhi;   // row r0+8
        float l10 = c1[0] + blo, l11 = c1[1] + bhi;   // row r0+16
        float l12 = c1[2] + blo, l13 = c1[3] + bhi;   // row r0+24
        s0 = __expf(l00) + __expf(l01);
        s1 = __expf(l02) + __expf(l03);
        s2 = __expf(l10) + __expf(l11);
        s3 = __expf(l12) + __expf(l13);
        if (cbase     == tw0) g_tgt[t * NN + r0]      = l00;
        if (cbase + 1 == tw0) g_tgt[t * NN + r0]      = l01;
        if (cbase     == tw1) g_tgt[t * NN + r0 + 8]  = l02;
        if (cbase + 1 == tw1) g_tgt[t * NN + r0 + 8]  = l03;
        if (cbase     == tw2) g_tgt[t * NN + r0 + 16] = l10;
        if (cbase + 1 == tw2) g_tgt[t * NN + r0 + 16] = l11;
        if (cbase     == tw3) g_tgt[t * NN + r0 + 24] = l12;
        if (cbase + 1 == tw3) g_tgt[t * NN + r0 + 24] = l13;
    }
    // reduce over the 4 lanes sharing each row (lane&3)
    #pragma unroll
    for (int m = 1; m <= 2; m <<= 1) {
        s0 += __shfl_xor_sync(0xffffffff, s0, m);
        s1 += __shfl_xor_sync(0xffffffff, s1, m);
        s2 += __shfl_xor_sync(0xffffffff, s2, m);
        s3 += __shfl_xor_sync(0xffffffff, s3, m);
    }
    if ((lane & 3) == 0) {
        sm[w][r0]      = s0;
        sm[w][r0 + 8]  = s1;
        sm[w][r0 + 16] = s2;
        sm[w][r0 + 24] = s3;
    }
    __syncthreads();
    if (w == 0) {
        float tot = 0.f;
        #pragma unroll
        for (int r = 0; r < 8; ++r) tot += sm[r][lane];
        g_Spart[((size_t)t * NBV + blockIdx.x) * NN + lane] = tot;
    }
}

// ---------------- epilogue: deterministic reduction + output write ----------------
__global__ void finalize_kernel(float* __restrict__ out, int out_size) {
    int n = blockIdx.x;
    int tid = threadIdx.x;

    float local = 0.f;
    if (tid < TS) {
        int t = tid;
        float S = 0.f;
        const float* sp = g_Spart + (size_t)t * NBV * NN + n;
        for (int b = 0; b < NBV; ++b) S += sp[b * NN];
        local = g_tgt[t * NN + n] - logf(S);
    }

    __shared__ float sred[256];
    sred[tid] = local;
    __syncthreads();
    #pragma unroll
    for (int s = 128; s > 0; s >>= 1) {
        if (tid < s) sred[tid] += sred[tid + s];
        __syncthreads();
    }

    if (tid == 0 && out_size >= NN) out[n] = sred[0];

    // h_final from pair layout; last step wrote g_h[TS & 1] = g_h[1]
    if (out_size >= NN + NN * HH) {
        const float* hf = g_h[TS & 1];
        for (int j = tid; j < HH; j += 256)
            out[NN + n * HH + j] = hf[(j >> 1) * 64 + n * 2 + (j & 1)];
    }
}

// ---------------- launcher (graph-capturable: kernel launches only) ----------------
extern "C" void kernel_launch(void* const* d_in, const int* in_sizes, int n_in,
                              void* d_out, int out_size) {
    const int*   words  = (const int*)  d_in[0];
    const float* hidden = (const float*)d_in[1];
    const float* embed  = (const float*)d_in[2];
    const float* w_ih   = (const float*)d_in[3];
    const float* w_hh   = (const float*)d_in[4];
    const float* b_ih   = (const float*)d_in[5];
    const float* b_hh   = (const float*)d_in[6];
    const float* emit_w = (const float*)d_in[7];
    const float* emit_b = (const float*)d_in[8];
    float* out = (float*)d_out;

    // Prologue: pack emit weights to bf16 fragments, init h, precompute all gi[t].
    pack_emit_kernel<<<VV, HH>>>(emit_w);
    hinit_kernel<<<(HH * NN + 255) / 256, 256>>>(hidden);
    gi_kernel<<<dim3(HH / 8, TS), 256>>>(words, embed, w_ih, b_ih);

    // 255 sequential timesteps, 2 kernels each (same stream -> serialized).
    for (int t = 0; t < TS; ++t) {
        gru_kernel<<<HH / 2, 256>>>(w_hh, b_hh, t);
        logits_kernel<<<NBV, 256>>>(words, emit_b, t);
    }

    finalize_kernel<<<NN, 256>>>(out, out_size);
}

// round 8
// speedup vs baseline: 12.0931x; 1.8046x over previous
#include <cuda_runtime.h>
#include <cuda_bf16.h>
#include <cstdint>
#include <cstddef>

// Problem constants
#define VV 32000
#define EE 512
#define HH 1024
#define NN 32
#define TT 256
#define TS 255            // timesteps = T-1
#define MROWS 8192        // padded rows (255*32 = 8160 -> 512 mtiles of 16)
#define NVC 250           // vocab column blocks in big CE GEMM (128 cols each)

#define MMA16816(acc, a, b)                                                     \
    asm volatile(                                                               \
        "mma.sync.aligned.m16n8k16.row.col.f32.bf16.bf16.f32 "                  \
        "{%0,%1,%2,%3}, {%4,%5,%6,%7}, {%8,%9}, {%0,%1,%2,%3};"                 \
        : "+f"(acc[0]), "+f"(acc[1]), "+f"(acc[2]), "+f"(acc[3])                \
        : "r"(a.x), "r"(a.y), "r"(a.z), "r"(a.w), "r"(b.x), "r"(b.y))

// ---------------- scratch (device globals; no allocation allowed) ----------------
__device__ __nv_bfloat16 g_Wpk[(size_t)VV * HH];      // emit_w bf16 B-fragment-major, 65.5 MB
__device__ __nv_bfloat16 g_WhhH[3 * HH * HH];         // w_hh hi bf16, A-fragment-major, 6.3 MB
__device__ __nv_bfloat16 g_WhhL[3 * HH * HH];         // w_hh lo bf16 (residual), 6.3 MB
__device__ float g_gi[(size_t)TS * 3 * HH * NN];      // precomputed input gates, 100 MB
__device__ float g_hf32[HH * NN];                     // exact fp32 hidden, [j][n]
__device__ __nv_bfloat16 g_hBH[2][4 * 64 * 32 * 4];   // h hi as B-fragments (ping-pong)
__device__ __nv_bfloat16 g_hBL[2][4 * 64 * 32 * 4];   // h lo as B-fragments (ping-pong)
__device__ __nv_bfloat16 g_hallA[(size_t)512 * 64 * 32 * 8]; // all h_{t+1} as A-frags, 16.8 MB
__device__ float g_SpartB[(size_t)MROWS * NVC];       // per-(row, vcol) partial sum-of-exp
__device__ float g_tgtlogit[MROWS];                   // target logit per row
__device__ int g_tgtword[MROWS];                      // target word per row (-1 pad)
__device__ unsigned g_barcnt;                         // grid barrier state
__device__ unsigned g_phase;

// ---------------- prologue: pack emit_w [V][H] fp32 -> bf16 B-fragment-major ----------------
__global__ void pack_emit_kernel(const float* __restrict__ emit_w) {
    int v = blockIdx.x;
    int k = threadIdx.x;            // blockDim = 1024 = HH
    float val = __ldg(emit_w + (size_t)v * HH + k);
    int bv = v >> 3, nn = v & 7;
    int bk = k >> 4, kk = k & 15;
    int lane = nn * 4 + ((kk & 7) >> 1);
    int reg  = kk >> 3;
    int half = kk & 1;
    size_t idx = (((size_t)(bv * 64 + bk)) * 32 + lane) * 4 + reg * 2 + half;
    g_Wpk[idx] = __float2bfloat16(val);
}

// ---------------- prologue: pack w_hh [3H][H] fp32 -> hi/lo bf16 A-fragment-major ----------------
__global__ void pack_whh_kernel(const float* __restrict__ w_hh) {
    int j = blockIdx.x;             // 0..3071
    int k = threadIdx.x;            // 0..1023
    float v = __ldg(w_hh + (size_t)j * HH + k);
    __nv_bfloat16 hi = __float2bfloat16(v);
    __nv_bfloat16 lo = __float2bfloat16(v - __bfloat162float(hi));
    int mt = j >> 4, r = j & 15, kt = k >> 4, c = k & 15;
    int fl = ((r & 7) << 2) | ((c & 7) >> 1);
    int rg = (r >> 3) + ((c >> 3) << 1);
    int hf = c & 1;
    size_t idx = (((size_t)(mt * 64 + kt)) * 32 + fl) * 8 + rg * 2 + hf;
    g_WhhH[idx] = hi;
    g_WhhL[idx] = lo;
}

// ---------------- prologue: init hidden state + barrier + hallA pad ----------------
__global__ void hinit_kernel(const float* __restrict__ hidden) {
    int idx = blockIdx.x * blockDim.x + threadIdx.x;   // 0..32767
    if (idx == 0) { g_barcnt = 0u; g_phase = 0u; }
    if (idx < HH * NN) {
        int j = idx >> 5, n = idx & 31;
        float hv = hidden[n * HH + j];
        g_hf32[j * NN + n] = hv;
        __nv_bfloat16 bh = __float2bfloat16(hv);
        __nv_bfloat16 bl = __float2bfloat16(hv - __bfloat162float(bh));
        int ktile = j >> 4, kk = j & 15, nt = n >> 3, nn = n & 7;
        int lane2 = (nn << 2) | ((kk & 7) >> 1);
        size_t bidx = (((size_t)(nt * 64 + ktile)) * 32 + lane2) * 4 + (kk >> 3) * 2 + (kk & 1);
        g_hBH[0][bidx] = bh;
        g_hBL[0][bidx] = bl;
        // zero padded A-fragment region (mtiles 510, 511): 2*64*32*8 = 32768 elems
        g_hallA[(size_t)510 * 64 * 32 * 8 + idx] = __float2bfloat16(0.f);
    }
}

// ---------------- prologue: target word per row ----------------
__global__ void tgt_kernel(const int* __restrict__ words) {
    int row = blockIdx.x * blockDim.x + threadIdx.x;  // 0..8191
    if (row < MROWS) {
        int t = row >> 5, n = row & 31;
        g_tgtword[row] = (t < TS) ? __ldg(words + n * TT + t + 1) : -1;
    }
}

// ---------------- prologue: precompute gi[t] = x_t @ w_ih.T + b_ih for ALL t ----------------
__global__ void __launch_bounds__(256) gi_kernel(const int* __restrict__ words,
                                                 const float* __restrict__ embed_w,
                                                 const float* __restrict__ w_ih,
                                                 const float* __restrict__ b_ih) {
    int lane = threadIdx.x & 31;
    int j = blockIdx.x * 8 + (threadIdx.x >> 5);
    int t = blockIdx.y;

    int word = __ldg(words + lane * TT + t);
    const float* xr = embed_w + (size_t)word * EE;
    const float* wr = w_ih + (size_t)j * EE;
    const float* wz = w_ih + (size_t)(HH + j) * EE;
    const float* wn = w_ih + (size_t)(2 * HH + j) * EE;

    float gr = 0.f, gz = 0.f, gn = 0.f;
    #pragma unroll 4
    for (int k = 0; k < EE; k += 4) {
        float4 x4 = __ldg(reinterpret_cast<const float4*>(xr + k));
        float4 a = __ldg(reinterpret_cast<const float4*>(wr + k));
        float4 b = __ldg(reinterpret_cast<const float4*>(wz + k));
        float4 c = __ldg(reinterpret_cast<const float4*>(wn + k));
        gr += a.x * x4.x + a.y * x4.y + a.z * x4.z + a.w * x4.w;
        gz += b.x * x4.x + b.y * x4.y + b.z * x4.z + b.w * x4.w;
        gn += c.x * x4.x + c.y * x4.y + c.z * x4.z + c.w * x4.w;
    }
    size_t base = ((size_t)t * 3 * HH + j) * NN + lane;
    g_gi[base]                       = gr + __ldg(b_ih + j);
    g_gi[base + (size_t)HH * NN]     = gz + __ldg(b_ih + HH + j);
    g_gi[base + (size_t)2 * HH * NN] = gn + __ldg(b_ih + 2 * HH + j);
}

// ---------------- persistent GRU chain: 255 steps in ONE kernel ----------------
// grid 64 blocks x 384 threads (12 warps). Block b owns j in [16b, 16b+16).
// warp w: gate g = w>>2 (r/z/n), ksplit ks = w&3 (16 ktiles each).
// gh = (Whi + Wlo) @ (hhi + hlo) via 3-term bf16 mma, fp32 accumulate.
__global__ void __launch_bounds__(384, 1) gru_chain_kernel(const float* __restrict__ b_hh) {
    __shared__ float sp[12][4][32][4];

    int tid = threadIdx.x;
    int lane = tid & 31;
    int w = tid >> 5;
    int b = blockIdx.x;
    int g = w >> 2, ks = w & 3;
    int mt = g * 64 + b;

    const uint4* AH = (const uint4*)g_WhhH;
    const uint4* AL = (const uint4*)g_WhhL;

    for (int t = 0; t < TS; ++t) {
        const uint2* BH = (const uint2*)g_hBH[t & 1];
        const uint2* BL = (const uint2*)g_hBL[t & 1];

        float acc[4][4] = {};
        int kt0 = ks * 16;
        #pragma unroll 4
        for (int kt = kt0; kt < kt0 + 16; ++kt) {
            uint4 ah = __ldg(&AH[((size_t)mt * 64 + kt) * 32 + lane]);
            uint4 al = __ldg(&AL[((size_t)mt * 64 + kt) * 32 + lane]);
            #pragma unroll
            for (int nt = 0; nt < 4; ++nt) {
                uint2 bh = __ldcg(&BH[(nt * 64 + kt) * 32 + lane]);   // bypass L1 (cross-SM producer)
                uint2 bl = __ldcg(&BL[(nt * 64 + kt) * 32 + lane]);
                MMA16816(acc[nt], ah, bh);
                MMA16816(acc[nt], ah, bl);
                MMA16816(acc[nt], al, bh);
            }
        }
        #pragma unroll
        for (int nt = 0; nt < 4; ++nt) {
            sp[w][nt][lane][0] = acc[nt][0];
            sp[w][nt][lane][1] = acc[nt][1];
            sp[w][nt][lane][2] = acc[nt][2];
            sp[w][nt][lane][3] = acc[nt][3];
        }
        __syncthreads();

        // Epilogue: 512 (j_local, n) pairs on 384 threads.
        for (int p = tid; p < 512; p += 384) {
            int jl = p >> 5, n = p & 31;
            int j = b * 16 + jl;
            int nt = n >> 3, c = n & 7;
            int lA = ((jl & 7) << 2) | (c >> 1);
            int rA = ((jl >> 3) << 1) | (c & 1);
            float s0 = 0.f, s1 = 0.f, s2 = 0.f;
            #pragma unroll
            for (int q = 0; q < 4; ++q) {
                s0 += sp[q][nt][lA][rA];
                s1 += sp[4 + q][nt][lA][rA];
                s2 += sp[8 + q][nt][lA][rA];
            }
            size_t gib = ((size_t)t * 3 * HH + j) * NN + n;
            float gr = __ldcs(&g_gi[gib]);
            float gz = __ldcs(&g_gi[gib + (size_t)HH * NN]);
            float gn = __ldcs(&g_gi[gib + (size_t)2 * HH * NN]);
            float hrt = s0 + __ldg(b_hh + j);
            float hzt = s1 + __ldg(b_hh + HH + j);
            float hnt = s2 + __ldg(b_hh + 2 * HH + j);

            float rr_ = 1.f / (1.f + expf(-(gr + hrt)));
            float zz_ = 1.f / (1.f + expf(-(gz + hzt)));
            float nn_ = tanhf(gn + rr_ * hnt);
            float ho = g_hf32[j * NN + n];
            float hv = (1.f - zz_) * nn_ + zz_ * ho;
            g_hf32[j * NN + n] = hv;

            __nv_bfloat16 bh16 = __float2bfloat16(hv);
            __nv_bfloat16 bl16 = __float2bfloat16(hv - __bfloat162float(bh16));

            // B-fragments of h_{t+1} for next step (ping-pong buffer)
            int kk = j & 15, nn8 = n & 7, ntB = n >> 3;
            size_t bidx = (((size_t)(ntB * 64 + b)) * 32 + ((nn8 << 2) | ((kk & 7) >> 1))) * 4
                          + (kk >> 3) * 2 + (kk & 1);
            int nb = (t + 1) & 1;
            g_hBH[nb][bidx] = bh16;
            g_hBL[nb][bidx] = bl16;

            // A-fragment of h_{t+1} for the big CE GEMM (single bf16)
            int mtg = t * 2 + (n >> 4);
            int rm = n & 15, cm = j & 15;
            size_t aidx = (((size_t)mtg * 64 + b) * 32 + (((rm & 7) << 2) | ((cm & 7) >> 1))) * 8
                          + ((rm >> 3) + ((cm >> 3) << 1)) * 2 + (cm & 1);
            g_hallA[aidx] = bh16;
        }

        __threadfence();
        __syncthreads();
        if (t < TS - 1) {
            if (tid == 0) {
                unsigned a = atomicAdd(&g_barcnt, 1u);
                if (a == (unsigned)(t * 64 + 63)) {
                    atomicAdd(&g_phase, 1u);
                }
                while (*(volatile unsigned*)&g_phase <= (unsigned)t) { }
            }
            __syncthreads();
            __threadfence();
        }
    }
}

// ---------------- big fused logits + cross-entropy GEMM ----------------
// C[8192, 32000] = hall[8192,1024] @ emit^T, fused exp-sum + target extraction.
// grid (250, 64), block 256 (8 warps). Block tile: 128 rows x 128 vocab cols.
// warp w handles vocab n8-tiles bv0 = vcol*16 + 2w (2 tiles) x all 8 row mtiles.
__global__ void __launch_bounds__(256) bigce_kernel(const float* __restrict__ emit_b) {
    __shared__ uint4 sA[2][8][32];     // double-buffered A fragments (8 KB)
    __shared__ float srow[8][128];

    int tid = threadIdx.x;
    int lane = tid & 31;
    int w = tid >> 5;
    int mrow = blockIdx.y;
    int vcol = blockIdx.x;
    int bv0 = vcol * 16 + w * 2;

    const uint4* AG = (const uint4*)g_hallA;
    const uint2* BG = (const uint2*)g_Wpk;

    float acc[2][8][4] = {};

    sA[0][w][lane] = __ldg(&AG[(((size_t)(mrow * 8 + w)) * 64 + 0) * 32 + lane]);
    __syncthreads();

    for (int kt = 0; kt < 64; ++kt) {
        int cb = kt & 1, nb = cb ^ 1;
        uint4 tmp = make_uint4(0, 0, 0, 0);
        if (kt < 63)
            tmp = __ldg(&AG[(((size_t)(mrow * 8 + w)) * 64 + (kt + 1)) * 32 + lane]);
        uint2 b0 = __ldg(&BG[(((size_t)bv0) * 64 + kt) * 32 + lane]);
        uint2 b1 = __ldg(&BG[(((size_t)(bv0 + 1)) * 64 + kt) * 32 + lane]);
        #pragma unroll
        for (int mt = 0; mt < 8; ++mt) {
            uint4 a = sA[cb][mt][lane];
            MMA16816(acc[0][mt], a, b0);
            MMA16816(acc[1][mt], a, b1);
        }
        if (kt < 63) sA[nb][w][lane] = tmp;
        __syncthreads();
    }

    // Epilogue: bias, exp-sum, target extraction.
    int cb0 = bv0 * 8 + (lane & 3) * 2;
    float e0 = __ldg(emit_b + cb0),     e1 = __ldg(emit_b + cb0 + 1);
    float e2 = __ldg(emit_b + cb0 + 8), e3 = __ldg(emit_b + cb0 + 9);

    #pragma unroll
    for (int mt = 0; mt < 8; ++mt) {
        #pragma unroll
        for (int rh = 0; rh < 2; ++rh) {
            int rl = mt * 16 + (lane >> 2) + rh * 8;
            int row = mrow * 128 + rl;
            int tw = __ldg(&g_tgtword[row]);
            float l0 = acc[0][mt][rh * 2 + 0] + e0;
            float l1 = acc[0][mt][rh * 2 + 1] + e1;
            float l2 = acc[1][mt][rh * 2 + 0] + e2;
            float l3 = acc[1][mt][rh * 2 + 1] + e3;
            float s = __expf(l0) + __expf(l1) + __expf(l2) + __expf(l3);
            if (cb0     == tw) g_tgtlogit[row] = l0;
            if (cb0 + 1 == tw) g_tgtlogit[row] = l1;
            if (cb0 + 8 == tw) g_tgtlogit[row] = l2;
            if (cb0 + 9 == tw) g_tgtlogit[row] = l3;
            s += __shfl_xor_sync(0xffffffffu, s, 1);
            s += __shfl_xor_sync(0xffffffffu, s, 2);
            if ((lane & 3) == 0) srow[w][rl] = s;
        }
    }
    __syncthreads();
    if (tid < 128) {
        float tot = 0.f;
        #pragma unroll
        for (int ww = 0; ww < 8; ++ww) tot += srow[ww][tid];
        g_SpartB[((size_t)(mrow * 128 + tid)) * NVC + vcol] = tot;
    }
}

// ---------------- epilogue: deterministic reduction + output write ----------------
__global__ void finalize_kernel(float* __restrict__ out, int out_size) {
    int n = blockIdx.x;
    int tid = threadIdx.x;

    float local = 0.f;
    if (tid < TS) {
        int row = tid * 32 + n;
        const float* sp = g_SpartB + (size_t)row * NVC;
        float S = 0.f;
        for (int v = 0; v < NVC; ++v) S += sp[v];
        local = g_tgtlogit[row] - logf(S);
    }

    __shared__ float sred[256];
    sred[tid] = local;
    __syncthreads();
    #pragma unroll
    for (int s = 128; s > 0; s >>= 1) {
        if (tid < s) sred[tid] += sred[tid + s];
        __syncthreads();
    }

    if (tid == 0 && out_size >= NN) out[n] = sred[0];

    if (out_size >= NN + NN * HH) {
        for (int j = tid; j < HH; j += 256)
            out[NN + n * HH + j] = g_hf32[j * NN + n];
    }
}

// ---------------- launcher (graph-capturable: kernel launches only) ----------------
extern "C" void kernel_launch(void* const* d_in, const int* in_sizes, int n_in,
                              void* d_out, int out_size) {
    const int*   words  = (const int*)  d_in[0];
    const float* hidden = (const float*)d_in[1];
    const float* embed  = (const float*)d_in[2];
    const float* w_ih   = (const float*)d_in[3];
    const float* w_hh   = (const float*)d_in[4];
    const float* b_ih   = (const float*)d_in[5];
    const float* b_hh   = (const float*)d_in[6];
    const float* emit_w = (const float*)d_in[7];
    const float* emit_b = (const float*)d_in[8];
    float* out = (float*)d_out;

    pack_emit_kernel<<<VV, HH>>>(emit_w);
    pack_whh_kernel<<<3 * HH, HH>>>(w_hh);
    hinit_kernel<<<(HH * NN + 255) / 256, 256>>>(hidden);
    tgt_kernel<<<MROWS / 256, 256>>>(words);
    gi_kernel<<<dim3(HH / 8, TS), 256>>>(words, embed, w_ih, b_ih);

    // Entire 255-step recurrence in one persistent kernel.
    gru_chain_kernel<<<64, 384>>>(b_hh);

    // One big fused logits + CE pass over all timesteps.
    bigce_kernel<<<dim3(NVC, 64), 256>>>(emit_b);

    finalize_kernel<<<NN, 256>>>(out, out_size);
}

// round 12
// speedup vs baseline: 21.3936x; 1.7691x over previous
#include <cuda_runtime.h>
#include <cuda_bf16.h>
#include <cstdint>
#include <cstddef>

// Problem constants
#define VV 32000
#define EE 512
#define HH 1024
#define NN 32
#define TT 256
#define TS 255            // timesteps = T-1
#define MROWS 8192        // padded rows (255*32 = 8160 -> 512 mtiles of 16)
#define NVC 250           // vocab column blocks in big CE GEMM (128 cols each)

#define MMA16816(acc, a, b)                                                     \
    asm volatile(                                                               \
        "mma.sync.aligned.m16n8k16.row.col.f32.bf16.bf16.f32 "                  \
        "{%0,%1,%2,%3}, {%4,%5,%6,%7}, {%8,%9}, {%0,%1,%2,%3};"                 \
        : "+f"(acc[0]), "+f"(acc[1]), "+f"(acc[2]), "+f"(acc[3])                \
        : "r"(a.x), "r"(a.y), "r"(a.z), "r"(a.w), "r"(b.x), "r"(b.y))

// ---------------- scratch (device globals; no allocation allowed) ----------------
__device__ __nv_bfloat16 g_Wpk[(size_t)VV * HH];      // emit_w bf16 B-fragment-major, 65.5 MB
__device__ __nv_bfloat16 g_WhhH[3 * HH * HH];         // w_hh hi bf16, A-frag-major
__device__ __nv_bfloat16 g_WhhL[3 * HH * HH];         // w_hh lo bf16 (residual)
__device__ __nv_bfloat16 g_WihH[3 * HH * EE];         // w_ih hi bf16, B-frag-major
__device__ __nv_bfloat16 g_WihL[3 * HH * EE];         // w_ih lo bf16
__device__ __nv_bfloat16 g_embAH[(size_t)MROWS * EE]; // gathered emb rows hi, A-frag-major
__device__ __nv_bfloat16 g_embAL[(size_t)MROWS * EE]; // gathered emb rows lo
__device__ float g_gi[(size_t)TS * 3 * HH * NN];      // input gates gi[t][g*H+j][n], 100 MB
__device__ float g_hf32[HH * NN];                     // exact fp32 hidden, [j][n]
__device__ __nv_bfloat16 g_hBH[2][4 * 64 * 32 * 4];   // h hi as B-fragments (ping-pong)
__device__ __nv_bfloat16 g_hBL[2][4 * 64 * 32 * 4];   // h lo as B-fragments (ping-pong)
__device__ __nv_bfloat16 g_hallA[(size_t)512 * 64 * 32 * 8]; // all h_{t+1} as A-frags, 16.8 MB
__device__ float g_SpartB[(size_t)MROWS * NVC];       // per-(row, vcol) partial sum-of-exp
__device__ float g_tgtlogit[MROWS];                   // target logit per row
__device__ int g_tgtword[MROWS];                      // target word per row (-1 pad)
__device__ unsigned g_barcnt;                         // grid barrier state
__device__ unsigned g_phase;

// ---------------- prologue: pack emit_w [V][H] fp32 -> bf16 B-fragment-major ----------------
__global__ void pack_emit_kernel(const float* __restrict__ emit_w) {
    int v = blockIdx.x;
    int k = threadIdx.x;            // blockDim = 1024 = HH
    float val = __ldg(emit_w + (size_t)v * HH + k);
    int bv = v >> 3, nn = v & 7;
    int bk = k >> 4, kk = k & 15;
    int lane = nn * 4 + ((kk & 7) >> 1);
    int reg  = kk >> 3;
    int half = kk & 1;
    size_t idx = (((size_t)(bv * 64 + bk)) * 32 + lane) * 4 + reg * 2 + half;
    g_Wpk[idx] = __float2bfloat16(val);
}

// ---------------- prologue: pack w_hh hi/lo bf16 A-fragment-major ----------------
__global__ void pack_whh_kernel(const float* __restrict__ w_hh) {
    int j = blockIdx.x;             // 0..3071
    int k = threadIdx.x;            // 0..1023
    float v = __ldg(w_hh + (size_t)j * HH + k);
    __nv_bfloat16 hi = __float2bfloat16(v);
    __nv_bfloat16 lo = __float2bfloat16(v - __bfloat162float(hi));
    int mt = j >> 4, r = j & 15, kt = k >> 4, c = k & 15;
    int fl = ((r & 7) << 2) | ((c & 7) >> 1);
    int rg = (r >> 3) + ((c >> 3) << 1);
    size_t idx = (((size_t)(mt * 64 + kt)) * 32 + fl) * 8 + rg * 2 + (c & 1);
    g_WhhH[idx] = hi;
    g_WhhL[idx] = lo;
}

// ---------------- prologue: pack w_ih hi/lo bf16 B-fragment-major ----------------
__global__ void pack_wih_kernel(const float* __restrict__ w_ih) {
    int j = blockIdx.x;             // 0..3071 (N dim)
    int k = threadIdx.x;            // 0..511  (K dim)
    float v = __ldg(w_ih + (size_t)j * EE + k);
    __nv_bfloat16 hi = __float2bfloat16(v);
    __nv_bfloat16 lo = __float2bfloat16(v - __bfloat162float(hi));
    int bn = j >> 3, nn = j & 7, bk = k >> 4, kk = k & 15;
    int lane = (nn << 2) | ((kk & 7) >> 1);
    size_t idx = (((size_t)(bn * 32 + bk)) * 32 + lane) * 4 + (kk >> 3) * 2 + (kk & 1);
    g_WihH[idx] = hi;
    g_WihL[idx] = lo;
}

// ---------------- prologue: gather embedding rows -> hi/lo A-fragment-major ----------------
__global__ void emb_pack_kernel(const int* __restrict__ words,
                                const float* __restrict__ embed_w) {
    int row = blockIdx.x;           // 0..8191
    int k = threadIdx.x;            // 0..511
    int t = row >> 5, n = row & 31;
    float v = 0.f;
    if (t < TS) {
        int word = __ldg(words + n * TT + t);
        v = __ldg(embed_w + (size_t)word * EE + k);
    }
    __nv_bfloat16 hi = __float2bfloat16(v);
    __nv_bfloat16 lo = __float2bfloat16(v - __bfloat162float(hi));
    int bm = row >> 4, rm = row & 15, bk = k >> 4, ck = k & 15;
    int fl = ((rm & 7) << 2) | ((ck & 7) >> 1);
    int rg = (rm >> 3) + ((ck >> 3) << 1);
    size_t idx = (((size_t)(bm * 32 + bk)) * 32 + fl) * 8 + rg * 2 + (ck & 1);
    g_embAH[idx] = hi;
    g_embAL[idx] = lo;
}

// ---------------- prologue: init hidden state + barrier + hallA pad ----------------
__global__ void hinit_kernel(const float* __restrict__ hidden) {
    int idx = blockIdx.x * blockDim.x + threadIdx.x;   // 0..32767
    if (idx == 0) { g_barcnt = 0u; g_phase = 0u; }
    if (idx < HH * NN) {
        int j = idx >> 5, n = idx & 31;
        float hv = hidden[n * HH + j];
        g_hf32[j * NN + n] = hv;
        __nv_bfloat16 bh = __float2bfloat16(hv);
        __nv_bfloat16 bl = __float2bfloat16(hv - __bfloat162float(bh));
        int ktile = j >> 4, kk = j & 15, nt = n >> 3, nn = n & 7;
        int lane2 = (nn << 2) | ((kk & 7) >> 1);
        size_t bidx = (((size_t)(nt * 64 + ktile)) * 32 + lane2) * 4 + (kk >> 3) * 2 + (kk & 1);
        g_hBH[0][bidx] = bh;
        g_hBL[0][bidx] = bl;
        // zero padded A-fragment region (mtiles 510, 511): 2*64*32*8 = 32768 elems
        g_hallA[(size_t)510 * 64 * 32 * 8 + idx] = __float2bfloat16(0.f);
    }
}

// ---------------- prologue: target word per row ----------------
__global__ void tgt_kernel(const int* __restrict__ words) {
    int row = blockIdx.x * blockDim.x + threadIdx.x;  // 0..8191
    if (row < MROWS) {
        int t = row >> 5, n = row & 31;
        g_tgtword[row] = (t < TS) ? __ldg(words + n * TT + t + 1) : -1;
    }
}

// ---------------- gi GEMM: [8192 x 512] @ [512 x 3072] via 3-term hi/lo mma.sync ----------------
// grid (64, 24), block 256 (8 warps). Block tile 128 rows x 128 cols.
__global__ void __launch_bounds__(256) gi_gemm_kernel(const float* __restrict__ b_ih) {
    __shared__ uint4 sAh[2][8][32];
    __shared__ uint4 sAl[2][8][32];

    int tid = threadIdx.x;
    int lane = tid & 31;
    int w = tid >> 5;
    int mr = blockIdx.x;            // 0..63  (128-row strip of 8192)
    int vc = blockIdx.y;            // 0..23  (128-col strip of 3072)
    int bn0 = vc * 16 + w * 2;

    const uint4* AH = (const uint4*)g_embAH;
    const uint4* AL = (const uint4*)g_embAL;
    const uint2* BH = (const uint2*)g_WihH;
    const uint2* BL = (const uint2*)g_WihL;

    float acc[2][8][4] = {};

    sAh[0][w][lane] = __ldg(&AH[(((size_t)(mr * 8 + w)) * 32 + 0) * 32 + lane]);
    sAl[0][w][lane] = __ldg(&AL[(((size_t)(mr * 8 + w)) * 32 + 0) * 32 + lane]);
    __syncthreads();

    for (int kt = 0; kt < 32; ++kt) {
        int cb = kt & 1, nb = cb ^ 1;
        uint4 th = make_uint4(0, 0, 0, 0), tl = make_uint4(0, 0, 0, 0);
        if (kt < 31) {
            th = __ldg(&AH[(((size_t)(mr * 8 + w)) * 32 + (kt + 1)) * 32 + lane]);
            tl = __ldg(&AL[(((size_t)(mr * 8 + w)) * 32 + (kt + 1)) * 32 + lane]);
        }
        uint2 bh0 = __ldg(&BH[(((size_t)bn0) * 32 + kt) * 32 + lane]);
        uint2 bl0 = __ldg(&BL[(((size_t)bn0) * 32 + kt) * 32 + lane]);
        uint2 bh1 = __ldg(&BH[(((size_t)(bn0 + 1)) * 32 + kt) * 32 + lane]);
        uint2 bl1 = __ldg(&BL[(((size_t)(bn0 + 1)) * 32 + kt) * 32 + lane]);
        #pragma unroll
        for (int mt = 0; mt < 8; ++mt) {
            uint4 a = sAh[cb][mt][lane];
            uint4 al = sAl[cb][mt][lane];
            MMA16816(acc[0][mt], a, bh0);
            MMA16816(acc[0][mt], a, bl0);
            MMA16816(acc[0][mt], al, bh0);
            MMA16816(acc[1][mt], a, bh1);
            MMA16816(acc[1][mt], a, bl1);
            MMA16816(acc[1][mt], al, bh1);
        }
        if (kt < 31) { sAh[nb][w][lane] = th; sAl[nb][w][lane] = tl; }
        __syncthreads();
    }

    // Epilogue: add bias, scatter to g_gi[t][col][n]
    #pragma unroll
    for (int nt = 0; nt < 2; ++nt) {
        int colb = (bn0 + nt) * 8 + (lane & 3) * 2;
        float bia0 = __ldg(b_ih + colb);
        float bia1 = __ldg(b_ih + colb + 1);
        #pragma unroll
        for (int mt = 0; mt < 8; ++mt) {
            #pragma unroll
            for (int rh = 0; rh < 2; ++rh) {
                int row = (mr * 8 + mt) * 16 + (lane >> 2) + rh * 8;
                int t = row >> 5, n = row & 31;
                if (t < TS) {
                    g_gi[((size_t)t * 3 * HH + colb) * NN + n]     = acc[nt][mt][rh * 2]     + bia0;
                    g_gi[((size_t)t * 3 * HH + colb + 1) * NN + n] = acc[nt][mt][rh * 2 + 1] + bia1;
                }
            }
        }
    }
}

// ---------------- persistent GRU chain: 255 steps in ONE kernel ----------------
// grid 64 blocks x 384 threads (12 warps). Block b owns j in [16b, 16b+16).
__global__ void __launch_bounds__(384, 1) gru_chain_kernel(const float* __restrict__ b_hh) {
    __shared__ float sp[12][4][32][4];

    int tid = threadIdx.x;
    int lane = tid & 31;
    int w = tid >> 5;
    int b = blockIdx.x;
    int g = w >> 2, ks = w & 3;
    int mt = g * 64 + b;

    const uint4* AH = (const uint4*)g_WhhH;
    const uint4* AL = (const uint4*)g_WhhL;

    for (int t = 0; t < TS; ++t) {
        const uint2* BH = (const uint2*)g_hBH[t & 1];
        const uint2* BL = (const uint2*)g_hBL[t & 1];

        float acc[4][4] = {};
        int kt0 = ks * 16;
        #pragma unroll 4
        for (int kt = kt0; kt < kt0 + 16; ++kt) {
            uint4 ah = __ldg(&AH[((size_t)mt * 64 + kt) * 32 + lane]);
            uint4 al = __ldg(&AL[((size_t)mt * 64 + kt) * 32 + lane]);
            #pragma unroll
            for (int nt = 0; nt < 4; ++nt) {
                uint2 bh = __ldcg(&BH[(nt * 64 + kt) * 32 + lane]);   // bypass L1 (cross-SM producer)
                uint2 bl = __ldcg(&BL[(nt * 64 + kt) * 32 + lane]);
                MMA16816(acc[nt], ah, bh);
                MMA16816(acc[nt], ah, bl);
                MMA16816(acc[nt], al, bh);
            }
        }
        #pragma unroll
        for (int nt = 0; nt < 4; ++nt) {
            sp[w][nt][lane][0] = acc[nt][0];
            sp[w][nt][lane][1] = acc[nt][1];
            sp[w][nt][lane][2] = acc[nt][2];
            sp[w][nt][lane][3] = acc[nt][3];
        }
        __syncthreads();

        // Epilogue: 512 (j_local, n) pairs on 384 threads.
        for (int p = tid; p < 512; p += 384) {
            int jl = p >> 5, n = p & 31;
            int j = b * 16 + jl;
            int nt = n >> 3, c = n & 7;
            int lA = ((jl & 7) << 2) | (c >> 1);
            int rA = ((jl >> 3) << 1) | (c & 1);
            float s0 = 0.f, s1 = 0.f, s2 = 0.f;
            #pragma unroll
            for (int q = 0; q < 4; ++q) {
                s0 += sp[q][nt][lA][rA];
                s1 += sp[4 + q][nt][lA][rA];
                s2 += sp[8 + q][nt][lA][rA];
            }
            size_t gib = ((size_t)t * 3 * HH + j) * NN + n;
            float gr = __ldcs(&g_gi[gib]);
            float gz = __ldcs(&g_gi[gib + (size_t)HH * NN]);
            float gn = __ldcs(&g_gi[gib + (size_t)2 * HH * NN]);
            float hrt = s0 + __ldg(b_hh + j);
            float hzt = s1 + __ldg(b_hh + HH + j);
            float hnt = s2 + __ldg(b_hh + 2 * HH + j);

            float rr_ = 1.f / (1.f + expf(-(gr + hrt)));
            float zz_ = 1.f / (1.f + expf(-(gz + hzt)));
            float nn_ = tanhf(gn + rr_ * hnt);
            float ho = g_hf32[j * NN + n];
            float hv = (1.f - zz_) * nn_ + zz_ * ho;
            g_hf32[j * NN + n] = hv;

            __nv_bfloat16 bh16 = __float2bfloat16(hv);
            __nv_bfloat16 bl16 = __float2bfloat16(hv - __bfloat162float(bh16));

            // B-fragments of h_{t+1} for next step (ping-pong buffer)
            int kk = j & 15, nn8 = n & 7, ntB = n >> 3;
            size_t bidx = (((size_t)(ntB * 64 + b)) * 32 + ((nn8 << 2) | ((kk & 7) >> 1))) * 4
                          + (kk >> 3) * 2 + (kk & 1);
            int nb = (t + 1) & 1;
            g_hBH[nb][bidx] = bh16;
            g_hBL[nb][bidx] = bl16;

            // A-fragment of h_{t+1} for the big CE GEMM (single bf16)
            int mtg = t * 2 + (n >> 4);
            int rm = n & 15, cm = j & 15;
            size_t aidx = (((size_t)mtg * 64 + b) * 32 + (((rm & 7) << 2) | ((cm & 7) >> 1))) * 8
                          + ((rm >> 3) + ((cm >> 3) << 1)) * 2 + (cm & 1);
            g_hallA[aidx] = bh16;
        }

        __threadfence();
        __syncthreads();
        if (t < TS - 1) {
            if (tid == 0) {
                unsigned a = atomicAdd(&g_barcnt, 1u);
                if (a == (unsigned)(t * 64 + 63)) atomicAdd(&g_phase, 1u);
                while (*(volatile unsigned*)&g_phase <= (unsigned)t) { }
            }
            __syncthreads();
            __threadfence();
        }
    }
}

// ---------------- big fused logits + cross-entropy GEMM (mma.sync) ----------------
// grid (64, 250): blockIdx.x = row strip (fast-varying -> concurrent blocks share
// the SAME vocab strip of B, keeping B reads in L2). Block tile: 128 rows x 128 cols.
__global__ void __launch_bounds__(256) bigce_kernel(const float* __restrict__ emit_b) {
    __shared__ uint4 sA[2][8][32];     // double-buffered A fragments (8 KB)
    __shared__ float srow[8][128];

    int tid = threadIdx.x;
    int lane = tid & 31;
    int w = tid >> 5;
    int mrow = blockIdx.x;          // 0..63
    int vcol = blockIdx.y;          // 0..249
    int bv0 = vcol * 16 + w * 2;

    const uint4* AG = (const uint4*)g_hallA;
    const uint2* BG = (const uint2*)g_Wpk;

    float acc[2][8][4] = {};

    sA[0][w][lane] = __ldg(&AG[(((size_t)(mrow * 8 + w)) * 64 + 0) * 32 + lane]);
    __syncthreads();

    for (int kt = 0; kt < 64; ++kt) {
        int cb = kt & 1, nb = cb ^ 1;
        uint4 tmp = make_uint4(0, 0, 0, 0);
        if (kt < 63)
            tmp = __ldg(&AG[(((size_t)(mrow * 8 + w)) * 64 + (kt + 1)) * 32 + lane]);
        uint2 b0 = __ldg(&BG[(((size_t)bv0) * 64 + kt) * 32 + lane]);
        uint2 b1 = __ldg(&BG[(((size_t)(bv0 + 1)) * 64 + kt) * 32 + lane]);
        #pragma unroll
        for (int mt = 0; mt < 8; ++mt) {
            uint4 a = sA[cb][mt][lane];
            MMA16816(acc[0][mt], a, b0);
            MMA16816(acc[1][mt], a, b1);
        }
        if (kt < 63) sA[nb][w][lane] = tmp;
        __syncthreads();
    }

    // Epilogue: bias, exp-sum, target extraction.
    int cb0 = bv0 * 8 + (lane & 3) * 2;
    float e0 = __ldg(emit_b + cb0),     e1 = __ldg(emit_b + cb0 + 1);
    float e2 = __ldg(emit_b + cb0 + 8), e3 = __ldg(emit_b + cb0 + 9);

    #pragma unroll
    for (int mt = 0; mt < 8; ++mt) {
        #pragma unroll
        for (int rh = 0; rh < 2; ++rh) {
            int rl = mt * 16 + (lane >> 2) + rh * 8;
            int row = mrow * 128 + rl;
            int tw = __ldg(&g_tgtword[row]);
            float l0 = acc[0][mt][rh * 2 + 0] + e0;
            float l1 = acc[0][mt][rh * 2 + 1] + e1;
            float l2 = acc[1][mt][rh * 2 + 0] + e2;
            float l3 = acc[1][mt][rh * 2 + 1] + e3;
            float s = __expf(l0) + __expf(l1) + __expf(l2) + __expf(l3);
            if (cb0     == tw) g_tgtlogit[row] = l0;
            if (cb0 + 1 == tw) g_tgtlogit[row] = l1;
            if (cb0 + 8 == tw) g_tgtlogit[row] = l2;
            if (cb0 + 9 == tw) g_tgtlogit[row] = l3;
            s += __shfl_xor_sync(0xffffffffu, s, 1);
            s += __shfl_xor_sync(0xffffffffu, s, 2);
            if ((lane & 3) == 0) srow[w][rl] = s;
        }
    }
    __syncthreads();
    if (tid < 128) {
        float tot = 0.f;
        #pragma unroll
        for (int ww = 0; ww < 8; ++ww) tot += srow[ww][tid];
        g_SpartB[((size_t)(mrow * 128 + tid)) * NVC + vcol] = tot;
    }
}

// ---------------- epilogue: deterministic reduction + output write ----------------
__global__ void finalize_kernel(float* __restrict__ out, int out_size) {
    int n = blockIdx.x;
    int tid = threadIdx.x;

    float local = 0.f;
    if (tid < TS) {
        int row = tid * 32 + n;
        const float* sp = g_SpartB + (size_t)row * NVC;
        float S = 0.f;
        for (int v = 0; v < NVC; ++v) S += sp[v];
        local = g_tgtlogit[row] - logf(S);
    }

    __shared__ float sred[256];
    sred[tid] = local;
    __syncthreads();
    #pragma unroll
    for (int s = 128; s > 0; s >>= 1) {
        if (tid < s) sred[tid] += sred[tid + s];
        __syncthreads();
    }

    if (tid == 0 && out_size >= NN) out[n] = sred[0];

    if (out_size >= NN + NN * HH) {
        for (int j = tid; j < HH; j += 256)
            out[NN + n * HH + j] = g_hf32[j * NN + n];
    }
}

// ---------------- launcher (graph-capturable: kernel launches only) ----------------
extern "C" void kernel_launch(void* const* d_in, const int* in_sizes, int n_in,
                              void* d_out, int out_size) {
    const int*   words  = (const int*)  d_in[0];
    const float* hidden = (const float*)d_in[1];
    const float* embed  = (const float*)d_in[2];
    const float* w_ih   = (const float*)d_in[3];
    const float* w_hh   = (const float*)d_in[4];
    const float* b_ih   = (const float*)d_in[5];
    const float* b_hh   = (const float*)d_in[6];
    const float* emit_w = (const float*)d_in[7];
    const float* emit_b = (const float*)d_in[8];
    float* out = (float*)d_out;

    pack_emit_kernel<<<VV, HH>>>(emit_w);
    pack_whh_kernel<<<3 * HH, HH>>>(w_hh);
    pack_wih_kernel<<<3 * HH, EE>>>(w_ih);
    hinit_kernel<<<(HH * NN + 255) / 256, 256>>>(hidden);
    tgt_kernel<<<MROWS / 256, 256>>>(words);
    emb_pack_kernel<<<MROWS, EE>>>(words, embed);

    // gi = emb @ w_ih^T + b_ih for ALL timesteps (tensor cores, 3-term hi/lo)
    gi_gemm_kernel<<<dim3(64, 24), 256>>>(b_ih);

    // Entire 255-step recurrence in one persistent kernel.
    gru_chain_kernel<<<64, 384>>>(b_hh);

    // One big fused logits + CE pass over all timesteps (mma.sync).
    bigce_kernel<<<dim3(64, NVC), 256>>>(emit_b);

    finalize_kernel<<<NN, 256>>>(out, out_size);
}